// round 6
// baseline (speedup 1.0000x reference)
#include <cuda_runtime.h>
#include <cuda_bf16.h>
#include <math.h>

#define ND 10000
#define EMAX 1000000
#define NB_EMB 10000
#define NT_EMB 1000
#define H 64
#define SCAN_BLK 1024
#define SCAN_NB 10          // 10 blocks * 1024 = 10240 >= ND (per edge set)

// ---------------- device scratch ---------------------------------------------
__device__ int   g_cnt_b[ND];
__device__ int   g_cnt_t[ND];
__device__ int   g_off_b[ND];
__device__ int   g_off_t[ND];
__device__ int   g_cur_b[ND];
__device__ int   g_cur_t[ND];
__device__ int   g_partials[2 * SCAN_NB];
__device__ int   g_sorted_b[EMAX];
__device__ int   g_sorted_t[EMAX];
__device__ __nv_bfloat16 g_Rb[NB_EMB * H];
__device__ __nv_bfloat16 g_Rt[NT_EMB * H];
__device__ float g_B[ND * H];
__device__ float g_T[ND * H];
__device__ float g_score[ND];

// ================= K1: hist(both edge sets) || prep ===========================
__global__ void k1_hist_prep(const float* __restrict__ be,
                             const float* __restrict__ te,
                             const int* __restrict__ dstb,
                             const int* __restrict__ dstt,
                             int n, int histBlocks) {
    if (blockIdx.x < histBlocks) {
        // ---- histogram partition ----
        int n8 = n >> 3;
        int total = 2 * n8;
        int g = blockIdx.x * blockDim.x + threadIdx.x;
        int stride = histBlocks * blockDim.x;
        for (int i = g; i < total; i += stride) {
            int which = (i >= n8);
            int gg = which ? i - n8 : i;
            const int4* d4 = (const int4*)(which ? dstt : dstb);
            int* cnt = which ? g_cnt_t : g_cnt_b;
            int4 da = d4[gg * 2], db = d4[gg * 2 + 1];
            atomicAdd(&cnt[da.x], 1);
            atomicAdd(&cnt[da.y], 1);
            atomicAdd(&cnt[da.z], 1);
            atomicAdd(&cnt[da.w], 1);
            atomicAdd(&cnt[db.x], 1);
            atomicAdd(&cnt[db.y], 1);
            atomicAdd(&cnt[db.z], 1);
            atomicAdd(&cnt[db.w], 1);
        }
        int rem = n & 7;
        if (g < rem) {
            int i = n - 1 - g;
            atomicAdd(&g_cnt_b[dstb[i]], 1);
            atomicAdd(&g_cnt_t[dstt[i]], 1);
        }
    } else {
        // ---- prep partition: relu + bf16 convert emb tables ----
        int pb = blockIdx.x - histBlocks;
        int pgrid = gridDim.x - histBlocks;
        int tid = pb * blockDim.x + threadIdx.x;
        int stride = pgrid * blockDim.x;
        for (int i = tid; i < NB_EMB * H; i += stride)
            g_Rb[i] = __float2bfloat16(fmaxf(be[i], 0.f));
        for (int i = tid; i < NT_EMB * H; i += stride)
            g_Rt[i] = __float2bfloat16(fmaxf(te[i], 0.f));
    }
}

// NOTE: counters must be zero before K1. They are zeroed at the END of the
// previous run? No — not allowed (determinism). Zero them in a tiny kernel
// launched before K1 (cheap, 1 block wave).
__global__ void zero_kernel() {
    int i = blockIdx.x * blockDim.x + threadIdx.x;
    int stride = gridDim.x * blockDim.x;
    for (; i < 2 * ND; i += stride) {
        if (i < ND) g_cnt_b[i] = 0;
        else        g_cnt_t[i - ND] = 0;
    }
}

// ================= K2: per-block partial sums =================================
__global__ void scan_partials_kernel() {
    __shared__ int sh[32];
    int b = blockIdx.x;                 // 0..2*SCAN_NB-1
    int which = (b >= SCAN_NB);
    int lb = which ? b - SCAN_NB : b;
    const int* cnt = which ? g_cnt_t : g_cnt_b;
    int idx = lb * SCAN_BLK + threadIdx.x;
    int v = (idx < ND) ? cnt[idx] : 0;
    #pragma unroll
    for (int o = 16; o > 0; o >>= 1)
        v += __shfl_down_sync(0xffffffffu, v, o);
    int lane = threadIdx.x & 31;
    int wid = threadIdx.x >> 5;
    if (lane == 0) sh[wid] = v;
    __syncthreads();
    if (wid == 0) {
        int w = (lane < SCAN_BLK / 32) ? sh[lane] : 0;
        #pragma unroll
        for (int o = 16; o > 0; o >>= 1)
            w += __shfl_down_sync(0xffffffffu, w, o);
        if (lane == 0) g_partials[b] = w;
    }
}

// ================= K3: per-block exclusive scan + emit (inline block offsets) =
__global__ void scan_emit_kernel() {
    __shared__ int wsum[32];
    __shared__ int sboff;
    int b = blockIdx.x;
    int which = (b >= SCAN_NB);
    int lb = which ? b - SCAN_NB : b;
    const int* cnt = which ? g_cnt_t : g_cnt_b;
    int* off = which ? g_off_t : g_off_b;
    int* cur = which ? g_cur_t : g_cur_b;

    if (threadIdx.x == 0) {
        int run = 0;
        int base = which ? SCAN_NB : 0;
        for (int i = 0; i < lb; i++) run += g_partials[base + i];
        sboff = run;
    }

    int idx = lb * SCAN_BLK + threadIdx.x;
    int v = (idx < ND) ? cnt[idx] : 0;
    int lane = threadIdx.x & 31;
    int wid = threadIdx.x >> 5;
    int inc = v;
    #pragma unroll
    for (int o = 1; o < 32; o <<= 1) {
        int t = __shfl_up_sync(0xffffffffu, inc, o);
        if (lane >= o) inc += t;
    }
    if (lane == 31) wsum[wid] = inc;
    __syncthreads();
    if (wid == 0) {
        int w = (lane < SCAN_BLK / 32) ? wsum[lane] : 0;
        #pragma unroll
        for (int o = 1; o < 32; o <<= 1) {
            int t = __shfl_up_sync(0xffffffffu, w, o);
            if (lane >= o) w += t;
        }
        wsum[lane] = w;
    }
    __syncthreads();
    int excl = inc - v + (wid > 0 ? wsum[wid - 1] : 0) + sboff;
    if (idx < ND) { off[idx] = excl; cur[idx] = excl; }
}

// ================= scatter body (one edge set) =================================
__device__ __forceinline__ void scatter_body(
    const int4* __restrict__ s4, const int4* __restrict__ d4,
    const int* __restrict__ ids, int* cur, int* out,
    const int* __restrict__ src, const int* __restrict__ dst,
    int n, int bid, int nblocks)
{
    int n8 = n >> 3;
    int g = bid * 256 + threadIdx.x;
    int stride = nblocks * 256;
    for (int gg = g; gg < n8; gg += stride) {
        int4 da = d4[gg * 2], db = d4[gg * 2 + 1];
        int4 sa = s4[gg * 2], sb = s4[gg * 2 + 1];
        int p0 = atomicAdd(&cur[da.x], 1);
        int p1 = atomicAdd(&cur[da.y], 1);
        int p2 = atomicAdd(&cur[da.z], 1);
        int p3 = atomicAdd(&cur[da.w], 1);
        int p4 = atomicAdd(&cur[db.x], 1);
        int p5 = atomicAdd(&cur[db.y], 1);
        int p6 = atomicAdd(&cur[db.z], 1);
        int p7 = atomicAdd(&cur[db.w], 1);
        int v0 = __ldg(&ids[sa.x]);
        int v1 = __ldg(&ids[sa.y]);
        int v2 = __ldg(&ids[sa.z]);
        int v3 = __ldg(&ids[sa.w]);
        int v4 = __ldg(&ids[sb.x]);
        int v5 = __ldg(&ids[sb.y]);
        int v6 = __ldg(&ids[sb.z]);
        int v7 = __ldg(&ids[sb.w]);
        out[p0] = v0; out[p1] = v1; out[p2] = v2; out[p3] = v3;
        out[p4] = v4; out[p5] = v5; out[p6] = v6; out[p7] = v7;
    }
    int rem = n & 7;
    if (g < rem) {
        int i = n - 1 - g;
        int p = atomicAdd(&cur[dst[i]], 1);
        out[p] = ids[src[i]];
    }
}

// ================= agg body (one dst segment, one warp) ========================
__device__ __forceinline__ void agg_body(
    int d, const int* __restrict__ off, const int* __restrict__ cnt,
    const int* __restrict__ srt, const __nv_bfloat16* __restrict__ emb,
    float* out, int lane)
{
    int s = off[d];
    int n = cnt[d];
    float ax = 0.f, ay = 0.f;
    int i = 0;
    for (; i + 8 <= n; i += 8) {
        int id[8];
        #pragma unroll
        for (int k = 0; k < 8; k++) id[k] = __ldg(&srt[s + i + k]);
        __nv_bfloat162 v[8];
        #pragma unroll
        for (int k = 0; k < 8; k++)
            v[k] = __ldg((const __nv_bfloat162*)(emb + (size_t)id[k] * H) + lane);
        #pragma unroll
        for (int k = 0; k < 8; k++) {
            float2 f = __bfloat1622float2(v[k]);
            ax += f.x; ay += f.y;
        }
    }
    for (; i < n; i++) {
        int id = __ldg(&srt[s + i]);
        float2 f = __bfloat1622float2(
            __ldg((const __nv_bfloat162*)(emb + (size_t)id * H) + lane));
        ax += f.x; ay += f.y;
    }
    float2 r; r.x = ax; r.y = ay;
    ((float2*)(out + (size_t)d * H))[lane] = r;
}

// ================= K4: scatter(bene) ===========================================
__global__ void k4_scatter_b(const int* __restrict__ srcb, const int* __restrict__ dstb,
                             const int* __restrict__ idsb, int n) {
    scatter_body((const int4*)srcb, (const int4*)dstb, idsb,
                 g_cur_b, g_sorted_b, srcb, dstb, n, blockIdx.x, gridDim.x);
}

// ================= K5: scatter(treat) || agg(bene) =============================
__global__ void k5_scatter_t_agg_b(const int* __restrict__ srct,
                                   const int* __restrict__ dstt,
                                   const int* __restrict__ idst,
                                   int n, int scBlocks) {
    if (blockIdx.x < scBlocks) {
        scatter_body((const int4*)srct, (const int4*)dstt, idst,
                     g_cur_t, g_sorted_t, srct, dstt, n, blockIdx.x, scBlocks);
    } else {
        int ab = blockIdx.x - scBlocks;
        int gw = (ab * 256 + threadIdx.x) >> 5;
        if (gw < ND)
            agg_body(gw, g_off_b, g_cnt_b, g_sorted_b, g_Rb, g_B,
                     threadIdx.x & 31);
    }
}

// ================= K6: agg(treat) ==============================================
__global__ void k6_agg_t() {
    int gw = (blockIdx.x * 256 + threadIdx.x) >> 5;
    if (gw < ND)
        agg_body(gw, g_off_t, g_cnt_t, g_sorted_t, g_Rt, g_T,
                 threadIdx.x & 31);
}

// ================= K7: fused per-node head =====================================
__global__ void head_kernel(const float* __restrict__ Wb, const float* __restrict__ bb,
                            const float* __restrict__ Wt, const float* __restrict__ bt,
                            const float* __restrict__ Wu, const float* __restrict__ bu,
                            const float* __restrict__ oW1, const float* __restrict__ ob1,
                            const float* __restrict__ oW2, const float* __restrict__ ob2) {
    __shared__ float sWb[64 * 64];
    __shared__ float sWt[64 * 64];
    __shared__ float sbb[64], sbt[64], sbu[64];
    __shared__ float sB[4][64], sT[4][64], sC[4][64], sD[4][64];

    int tid = threadIdx.x;
    for (int k = tid; k < 4096; k += 256) { sWb[k] = Wb[k]; sWt[k] = Wt[k]; }
    if (tid < 64) { sbb[tid] = bb[tid]; sbt[tid] = bt[tid]; sbu[tid] = bu[tid]; }
    __syncthreads();

    int grp = tid >> 6;
    int j   = tid & 63;

    for (int row = blockIdx.x * 4 + grp; row < ND; row += gridDim.x * 4) {
        sB[grp][j] = g_B[(size_t)row * 64 + j];
        sT[grp][j] = g_T[(size_t)row * 64 + j];
        float degb = (float)g_cnt_b[row];
        float degt = (float)g_cnt_t[row];
        __syncthreads();

        float c = 0.f;
        #pragma unroll 16
        for (int k = 0; k < 64; k++) {
            c += sB[grp][k] * sWb[k * 64 + j];
            c += sT[grp][k] * sWt[k * 64 + j];
        }
        c = 0.5f * (c + degb * sbb[j] + degt * sbt[j]);
        sC[grp][j] = c;
        __syncthreads();

        float dd = sbu[j];
        #pragma unroll 16
        for (int k = 0; k < 64; k++)
            dd += sC[grp][k] * __ldg(&Wu[k * 64 + j]);
        sD[grp][j] = fmaxf(dd, 0.f);
        __syncthreads();

        if (j < 32) {
            float h = __ldg(&ob1[j]);
            #pragma unroll 16
            for (int k = 0; k < 64; k++)
                h += sD[grp][k] * __ldg(&oW1[k * 32 + j]);
            h = fmaxf(h, 0.f);
            float p = h * __ldg(&oW2[j]);
            #pragma unroll
            for (int o = 16; o > 0; o >>= 1)
                p += __shfl_down_sync(0xffffffffu, p, o);
            if (j == 0)
                g_score[row] = 1.f / (1.f + expf(-(p + __ldg(ob2))));
        }
        __syncthreads();
    }
}

// ================= K8: output gather, float4 writes ============================
__global__ void out_gather_kernel(const int* __restrict__ inst2type,
                                  float* __restrict__ out, int n) {
    int n4 = n >> 2;
    int i = blockIdx.x * blockDim.x + threadIdx.x;
    int stride = gridDim.x * blockDim.x;
    for (int g = i; g < n4; g += stride) {
        int4 t = ((const int4*)inst2type)[g];
        float4 r;
        r.x = g_score[t.x];
        r.y = g_score[t.y];
        r.z = g_score[t.z];
        r.w = g_score[t.w];
        ((float4*)out)[g] = r;
    }
    int rem = n & 3;
    if (i < rem)
        out[n - 1 - i] = g_score[inst2type[n - 1 - i]];
}

// ================= launch ======================================================
extern "C" void kernel_launch(void* const* d_in, const int* in_sizes, int n_in,
                              void* d_out, int out_size) {
    const int*   bene_ids      = (const int*)d_in[0];
    const int*   treatment_ids = (const int*)d_in[2];
    const int*   b2d_src       = (const int*)d_in[3];
    const int*   b2d_dst       = (const int*)d_in[4];
    const int*   t2d_src       = (const int*)d_in[5];
    const int*   t2d_dst       = (const int*)d_in[6];
    const int*   inst2type     = (const int*)d_in[7];
    const float* bene_emb      = (const float*)d_in[8];
    const float* treat_emb     = (const float*)d_in[10];
    const float* Wb1 = (const float*)d_in[17];
    const float* bb1 = (const float*)d_in[18];
    const float* Wt1 = (const float*)d_in[19];
    const float* bt1 = (const float*)d_in[20];
    const float* Wu1 = (const float*)d_in[21];
    const float* bu1 = (const float*)d_in[22];
    const float* oW1 = (const float*)d_in[23];
    const float* ob1 = (const float*)d_in[24];
    const float* oW2 = (const float*)d_in[25];
    const float* ob2 = (const float*)d_in[26];

    int E     = in_sizes[3];
    int NINST = in_sizes[7];

    zero_kernel<<<40, 256>>>();

    // K1: hist (both) || prep, block-partitioned
    {
        int histBlocks = (2 * (E >> 3) + 255) / 256;
        if (histBlocks > 1024) histBlocks = 1024;
        if (histBlocks < 1) histBlocks = 1;
        int prepBlocks = 160;
        k1_hist_prep<<<histBlocks + prepBlocks, 256>>>(
            bene_emb, treat_emb, b2d_dst, t2d_dst, E, histBlocks);
    }
    scan_partials_kernel<<<2 * SCAN_NB, SCAN_BLK>>>();
    scan_emit_kernel<<<2 * SCAN_NB, SCAN_BLK>>>();

    int scB = ((E >> 3) + 255) / 256;   // scatter blocks per edge set
    if (scB > 1024) scB = 1024;
    if (scB < 1) scB = 1;
    int aggB = (ND * 32 + 255) / 256;   // 1250 blocks: one warp per dst

    // K4: scatter bene
    k4_scatter_b<<<scB, 256>>>(b2d_src, b2d_dst, bene_ids, E);
    // K5: scatter treat || agg bene
    k5_scatter_t_agg_b<<<scB + aggB, 256>>>(t2d_src, t2d_dst, treatment_ids, E, scB);
    // K6: agg treat
    k6_agg_t<<<aggB, 256>>>();

    head_kernel<<<250, 256>>>(Wb1, bb1, Wt1, bt1, Wu1, bu1, oW1, ob1, oW2, ob2);
    {
        int blocks = ((NINST >> 2) + 255) / 256;
        if (blocks < 1) blocks = 1;
        out_gather_kernel<<<blocks, 256>>>(inst2type, (float*)d_out, NINST);
    }
}

// round 7
// speedup vs baseline: 1.2265x; 1.2265x over previous
#include <cuda_runtime.h>
#include <cuda_bf16.h>
#include <math.h>

#define ND 10000
#define NB_EMB 10000
#define NT_EMB 1000
#define H 64
#define CAP 256            // bucket capacity per dst (mean deg 100, max ~143)

// ---------------- device scratch ---------------------------------------------
__device__ int   g_cnt_b[ND];
__device__ int   g_cnt_t[ND];
__device__ int   g_bucket_b[ND * CAP];
__device__ int   g_bucket_t[ND * CAP];
__device__ __nv_bfloat16 g_Rb[NB_EMB * H];
__device__ __nv_bfloat16 g_Rt[NT_EMB * H];
__device__ float g_B[ND * H];
__device__ float g_T[ND * H];
__device__ float g_score[ND];

// ================= K0: zero counters + relu+bf16 convert emb tables ===========
__global__ void zero_prep_kernel(const float* __restrict__ be,
                                 const float* __restrict__ te) {
    int tid = blockIdx.x * blockDim.x + threadIdx.x;
    int stride = gridDim.x * blockDim.x;
    for (int i = tid; i < 2 * ND; i += stride) {
        if (i < ND) g_cnt_b[i] = 0;
        else        g_cnt_t[i - ND] = 0;
    }
    for (int i = tid; i < NB_EMB * H; i += stride)
        g_Rb[i] = __float2bfloat16(fmaxf(be[i], 0.f));
    for (int i = tid; i < NT_EMB * H; i += stride)
        g_Rt[i] = __float2bfloat16(fmaxf(te[i], 0.f));
}

// ================= K1: bucket scatter, both edge sets, 8 edges/thread =========
__global__ void scatter_kernel(const int* __restrict__ srcb, const int* __restrict__ dstb,
                               const int* __restrict__ idsb,
                               const int* __restrict__ srct, const int* __restrict__ dstt,
                               const int* __restrict__ idst, int n) {
    int n8 = n >> 3;
    int total = 2 * n8;
    int g = blockIdx.x * blockDim.x + threadIdx.x;
    int stride = gridDim.x * blockDim.x;
    for (int i = g; i < total; i += stride) {
        int which = (i >= n8);
        int gg = which ? i - n8 : i;
        const int4* s4 = (const int4*)(which ? srct : srcb);
        const int4* d4 = (const int4*)(which ? dstt : dstb);
        const int* ids = which ? idst : idsb;
        int* cnt = which ? g_cnt_t : g_cnt_b;
        int* bkt = which ? g_bucket_t : g_bucket_b;
        int4 da = d4[gg * 2], db = d4[gg * 2 + 1];
        int4 sa = s4[gg * 2], sb = s4[gg * 2 + 1];
        // 8 independent atomic/gather chains in flight
        int p0 = atomicAdd(&cnt[da.x], 1);
        int p1 = atomicAdd(&cnt[da.y], 1);
        int p2 = atomicAdd(&cnt[da.z], 1);
        int p3 = atomicAdd(&cnt[da.w], 1);
        int p4 = atomicAdd(&cnt[db.x], 1);
        int p5 = atomicAdd(&cnt[db.y], 1);
        int p6 = atomicAdd(&cnt[db.z], 1);
        int p7 = atomicAdd(&cnt[db.w], 1);
        int v0 = __ldg(&ids[sa.x]);
        int v1 = __ldg(&ids[sa.y]);
        int v2 = __ldg(&ids[sa.z]);
        int v3 = __ldg(&ids[sa.w]);
        int v4 = __ldg(&ids[sb.x]);
        int v5 = __ldg(&ids[sb.y]);
        int v6 = __ldg(&ids[sb.z]);
        int v7 = __ldg(&ids[sb.w]);
        bkt[da.x * CAP + p0] = v0;
        bkt[da.y * CAP + p1] = v1;
        bkt[da.z * CAP + p2] = v2;
        bkt[da.w * CAP + p3] = v3;
        bkt[db.x * CAP + p4] = v4;
        bkt[db.y * CAP + p5] = v5;
        bkt[db.z * CAP + p6] = v6;
        bkt[db.w * CAP + p7] = v7;
    }
    int rem = n & 7;
    if (g < rem) {
        int i = n - 1 - g;
        int pb = atomicAdd(&g_cnt_b[dstb[i]], 1);
        g_bucket_b[dstb[i] * CAP + pb] = idsb[srcb[i]];
        int pt = atomicAdd(&g_cnt_t[dstt[i]], 1);
        g_bucket_t[dstt[i] * CAP + pt] = idst[srct[i]];
    }
}

// ================= K2: segment aggregation, one warp per dst ===================
__device__ __forceinline__ void agg_body(
    int d, const int* __restrict__ cnt, const int* __restrict__ bkt,
    const __nv_bfloat16* __restrict__ emb, float* out, int lane)
{
    int s = d * CAP;
    int n = cnt[d];
    float ax = 0.f, ay = 0.f;
    int i = 0;
    for (; i + 8 <= n; i += 8) {
        int id[8];
        #pragma unroll
        for (int k = 0; k < 8; k++) id[k] = __ldg(&bkt[s + i + k]);
        __nv_bfloat162 v[8];
        #pragma unroll
        for (int k = 0; k < 8; k++)
            v[k] = __ldg((const __nv_bfloat162*)(emb + (size_t)id[k] * H) + lane);
        #pragma unroll
        for (int k = 0; k < 8; k++) {
            float2 f = __bfloat1622float2(v[k]);
            ax += f.x; ay += f.y;
        }
    }
    for (; i < n; i++) {
        int id = __ldg(&bkt[s + i]);
        float2 f = __bfloat1622float2(
            __ldg((const __nv_bfloat162*)(emb + (size_t)id * H) + lane));
        ax += f.x; ay += f.y;
    }
    float2 r; r.x = ax; r.y = ay;
    ((float2*)(out + (size_t)d * H))[lane] = r;
}

__global__ void agg_kernel() {
    int gw = (blockIdx.x * blockDim.x + threadIdx.x) >> 5;
    int lane = threadIdx.x & 31;
    if (gw >= 2 * ND) return;
    if (gw < ND) agg_body(gw,      g_cnt_b, g_bucket_b, g_Rb, g_B, lane);
    else         agg_body(gw - ND, g_cnt_t, g_bucket_t, g_Rt, g_T, lane);
}

// ================= K3: fused per-node head =====================================
__global__ void head_kernel(const float* __restrict__ Wb, const float* __restrict__ bb,
                            const float* __restrict__ Wt, const float* __restrict__ bt,
                            const float* __restrict__ Wu, const float* __restrict__ bu,
                            const float* __restrict__ oW1, const float* __restrict__ ob1,
                            const float* __restrict__ oW2, const float* __restrict__ ob2) {
    __shared__ float sWb[64 * 64];
    __shared__ float sWt[64 * 64];
    __shared__ float sbb[64], sbt[64], sbu[64];
    __shared__ float sB[4][64], sT[4][64], sC[4][64], sD[4][64];

    int tid = threadIdx.x;
    for (int k = tid; k < 4096; k += 256) { sWb[k] = Wb[k]; sWt[k] = Wt[k]; }
    if (tid < 64) { sbb[tid] = bb[tid]; sbt[tid] = bt[tid]; sbu[tid] = bu[tid]; }
    __syncthreads();

    int grp = tid >> 6;
    int j   = tid & 63;

    for (int row = blockIdx.x * 4 + grp; row < ND; row += gridDim.x * 4) {
        sB[grp][j] = g_B[(size_t)row * 64 + j];
        sT[grp][j] = g_T[(size_t)row * 64 + j];
        float degb = (float)g_cnt_b[row];
        float degt = (float)g_cnt_t[row];
        __syncthreads();

        float c = 0.f;
        #pragma unroll 16
        for (int k = 0; k < 64; k++) {
            c += sB[grp][k] * sWb[k * 64 + j];
            c += sT[grp][k] * sWt[k * 64 + j];
        }
        c = 0.5f * (c + degb * sbb[j] + degt * sbt[j]);
        sC[grp][j] = c;
        __syncthreads();

        float dd = sbu[j];
        #pragma unroll 16
        for (int k = 0; k < 64; k++)
            dd += sC[grp][k] * __ldg(&Wu[k * 64 + j]);
        sD[grp][j] = fmaxf(dd, 0.f);
        __syncthreads();

        if (j < 32) {
            float h = __ldg(&ob1[j]);
            #pragma unroll 16
            for (int k = 0; k < 64; k++)
                h += sD[grp][k] * __ldg(&oW1[k * 32 + j]);
            h = fmaxf(h, 0.f);
            float p = h * __ldg(&oW2[j]);
            #pragma unroll
            for (int o = 16; o > 0; o >>= 1)
                p += __shfl_down_sync(0xffffffffu, p, o);
            if (j == 0)
                g_score[row] = 1.f / (1.f + expf(-(p + __ldg(ob2))));
        }
        __syncthreads();
    }
}

// ================= K4: output gather, float4 writes ============================
__global__ void out_gather_kernel(const int* __restrict__ inst2type,
                                  float* __restrict__ out, int n) {
    int n4 = n >> 2;
    int i = blockIdx.x * blockDim.x + threadIdx.x;
    int stride = gridDim.x * blockDim.x;
    for (int g = i; g < n4; g += stride) {
        int4 t = ((const int4*)inst2type)[g];
        float4 r;
        r.x = g_score[t.x];
        r.y = g_score[t.y];
        r.z = g_score[t.z];
        r.w = g_score[t.w];
        ((float4*)out)[g] = r;
    }
    int rem = n & 3;
    if (i < rem)
        out[n - 1 - i] = g_score[inst2type[n - 1 - i]];
}

// ================= launch ======================================================
extern "C" void kernel_launch(void* const* d_in, const int* in_sizes, int n_in,
                              void* d_out, int out_size) {
    const int*   bene_ids      = (const int*)d_in[0];
    const int*   treatment_ids = (const int*)d_in[2];
    const int*   b2d_src       = (const int*)d_in[3];
    const int*   b2d_dst       = (const int*)d_in[4];
    const int*   t2d_src       = (const int*)d_in[5];
    const int*   t2d_dst       = (const int*)d_in[6];
    const int*   inst2type     = (const int*)d_in[7];
    const float* bene_emb      = (const float*)d_in[8];
    const float* treat_emb     = (const float*)d_in[10];
    const float* Wb1 = (const float*)d_in[17];
    const float* bb1 = (const float*)d_in[18];
    const float* Wt1 = (const float*)d_in[19];
    const float* bt1 = (const float*)d_in[20];
    const float* Wu1 = (const float*)d_in[21];
    const float* bu1 = (const float*)d_in[22];
    const float* oW1 = (const float*)d_in[23];
    const float* ob1 = (const float*)d_in[24];
    const float* oW2 = (const float*)d_in[25];
    const float* ob2 = (const float*)d_in[26];

    int E     = in_sizes[3];
    int NINST = in_sizes[7];

    zero_prep_kernel<<<160, 256>>>(bene_emb, treat_emb);

    {
        int blocks = (2 * (E >> 3) + 255) / 256;
        if (blocks > 2048) blocks = 2048;
        if (blocks < 1) blocks = 1;
        scatter_kernel<<<blocks, 256>>>(b2d_src, b2d_dst, bene_ids,
                                        t2d_src, t2d_dst, treatment_ids, E);
    }
    {
        int blocks = (2 * ND * 32 + 255) / 256;   // one warp per dst segment
        agg_kernel<<<blocks, 256>>>();
    }
    head_kernel<<<250, 256>>>(Wb1, bb1, Wt1, bt1, Wu1, bu1, oW1, ob1, oW2, ob2);
    {
        int blocks = ((NINST >> 2) + 255) / 256;
        if (blocks < 1) blocks = 1;
        out_gather_kernel<<<blocks, 256>>>(inst2type, (float*)d_out, NINST);
    }
}

// round 8
// speedup vs baseline: 1.4703x; 1.1988x over previous
#include <cuda_runtime.h>
#include <cuda_bf16.h>
#include <math.h>

#define ND 10000
#define NB_EMB 10000
#define NT_EMB 1000
#define H 64
#define CAP 256            // bucket capacity per dst (mean deg 100, max ~143)

// ---------------- device scratch ---------------------------------------------
__device__ int   g_cnt_b[ND];
__device__ int   g_cnt_t[ND];
__device__ int   g_bucket_b[ND * CAP];
__device__ int   g_bucket_t[ND * CAP];
__device__ __nv_bfloat16 g_Rb[NB_EMB * H];
__device__ __nv_bfloat16 g_Rt[NT_EMB * H];
__device__ float g_B[ND * H];
__device__ float g_T[ND * H];
__device__ float g_Wbu[H * H];   // 0.5 * Wb1 @ Wu1
__device__ float g_Wtu[H * H];   // 0.5 * Wt1 @ Wu1
__device__ float g_vbb[H];       // 0.5 * bb1 @ Wu1
__device__ float g_vbt[H];       // 0.5 * bt1 @ Wu1
__device__ float g_score[ND];

// ================= K0: precompute + zero counters + relu/bf16 convert =========
// blocks [0,32): fold Wb@Wu / Wt@Wu.  block 32: bias vectors.
// blocks [33, 33+prep): zero counters + convert emb tables.
__global__ void prep_kernel(const float* __restrict__ be,
                            const float* __restrict__ te,
                            const float* __restrict__ Wb, const float* __restrict__ bb,
                            const float* __restrict__ Wt, const float* __restrict__ bt,
                            const float* __restrict__ Wu) {
    if (blockIdx.x < 32) {
        int t = blockIdx.x * 256 + threadIdx.x;      // 0..8191
        int mat = t >> 12;                           // 0: Wbu, 1: Wtu
        int k = (t >> 6) & 63;
        int j = t & 63;
        const float* W = mat ? Wt : Wb;
        float acc = 0.f;
        #pragma unroll 16
        for (int m = 0; m < 64; m++)
            acc += __ldg(&W[k * 64 + m]) * __ldg(&Wu[m * 64 + j]);
        (mat ? g_Wtu : g_Wbu)[k * 64 + j] = 0.5f * acc;
    } else if (blockIdx.x == 32) {
        int t = threadIdx.x;
        if (t < 128) {
            int which = t >> 6;                      // 0: vbb, 1: vbt
            int j = t & 63;
            const float* v = which ? bt : bb;
            float acc = 0.f;
            #pragma unroll 16
            for (int m = 0; m < 64; m++)
                acc += __ldg(&v[m]) * __ldg(&Wu[m * 64 + j]);
            (which ? g_vbt : g_vbb)[j] = 0.5f * acc;
        }
    } else {
        int pb = blockIdx.x - 33;
        int pgrid = gridDim.x - 33;
        int tid = pb * blockDim.x + threadIdx.x;
        int stride = pgrid * blockDim.x;
        for (int i = tid; i < 2 * ND; i += stride) {
            if (i < ND) g_cnt_b[i] = 0;
            else        g_cnt_t[i - ND] = 0;
        }
        for (int i = tid; i < NB_EMB * H; i += stride)
            g_Rb[i] = __float2bfloat16(fmaxf(be[i], 0.f));
        for (int i = tid; i < NT_EMB * H; i += stride)
            g_Rt[i] = __float2bfloat16(fmaxf(te[i], 0.f));
    }
}

// ================= K1: bucket scatter, both edge sets, 8 edges/thread =========
__global__ void scatter_kernel(const int* __restrict__ srcb, const int* __restrict__ dstb,
                               const int* __restrict__ idsb,
                               const int* __restrict__ srct, const int* __restrict__ dstt,
                               const int* __restrict__ idst, int n) {
    int n8 = n >> 3;
    int total = 2 * n8;
    int g = blockIdx.x * blockDim.x + threadIdx.x;
    int stride = gridDim.x * blockDim.x;
    for (int i = g; i < total; i += stride) {
        int which = (i >= n8);
        int gg = which ? i - n8 : i;
        const int4* s4 = (const int4*)(which ? srct : srcb);
        const int4* d4 = (const int4*)(which ? dstt : dstb);
        const int* ids = which ? idst : idsb;
        int* cnt = which ? g_cnt_t : g_cnt_b;
        int* bkt = which ? g_bucket_t : g_bucket_b;
        int4 da = d4[gg * 2], db = d4[gg * 2 + 1];
        int4 sa = s4[gg * 2], sb = s4[gg * 2 + 1];
        int p0 = atomicAdd(&cnt[da.x], 1);
        int p1 = atomicAdd(&cnt[da.y], 1);
        int p2 = atomicAdd(&cnt[da.z], 1);
        int p3 = atomicAdd(&cnt[da.w], 1);
        int p4 = atomicAdd(&cnt[db.x], 1);
        int p5 = atomicAdd(&cnt[db.y], 1);
        int p6 = atomicAdd(&cnt[db.z], 1);
        int p7 = atomicAdd(&cnt[db.w], 1);
        int v0 = __ldg(&ids[sa.x]);
        int v1 = __ldg(&ids[sa.y]);
        int v2 = __ldg(&ids[sa.z]);
        int v3 = __ldg(&ids[sa.w]);
        int v4 = __ldg(&ids[sb.x]);
        int v5 = __ldg(&ids[sb.y]);
        int v6 = __ldg(&ids[sb.z]);
        int v7 = __ldg(&ids[sb.w]);
        bkt[da.x * CAP + p0] = v0;
        bkt[da.y * CAP + p1] = v1;
        bkt[da.z * CAP + p2] = v2;
        bkt[da.w * CAP + p3] = v3;
        bkt[db.x * CAP + p4] = v4;
        bkt[db.y * CAP + p5] = v5;
        bkt[db.z * CAP + p6] = v6;
        bkt[db.w * CAP + p7] = v7;
    }
    int rem = n & 7;
    if (g < rem) {
        int i = n - 1 - g;
        int pb = atomicAdd(&g_cnt_b[dstb[i]], 1);
        g_bucket_b[dstb[i] * CAP + pb] = idsb[srcb[i]];
        int pt = atomicAdd(&g_cnt_t[dstt[i]], 1);
        g_bucket_t[dstt[i] * CAP + pt] = idst[srct[i]];
    }
}

// ================= K2: segment aggregation, one warp per dst ===================
__device__ __forceinline__ void agg_body(
    int d, const int* __restrict__ cnt, const int* __restrict__ bkt,
    const __nv_bfloat16* __restrict__ emb, float* out, int lane)
{
    int s = d * CAP;
    int n = cnt[d];
    float ax = 0.f, ay = 0.f;
    int i = 0;
    for (; i + 8 <= n; i += 8) {
        int id[8];
        #pragma unroll
        for (int k = 0; k < 8; k++) id[k] = __ldg(&bkt[s + i + k]);
        __nv_bfloat162 v[8];
        #pragma unroll
        for (int k = 0; k < 8; k++)
            v[k] = __ldg((const __nv_bfloat162*)(emb + (size_t)id[k] * H) + lane);
        #pragma unroll
        for (int k = 0; k < 8; k++) {
            float2 f = __bfloat1622float2(v[k]);
            ax += f.x; ay += f.y;
        }
    }
    for (; i < n; i++) {
        int id = __ldg(&bkt[s + i]);
        float2 f = __bfloat1622float2(
            __ldg((const __nv_bfloat162*)(emb + (size_t)id * H) + lane));
        ax += f.x; ay += f.y;
    }
    float2 r; r.x = ax; r.y = ay;
    ((float2*)(out + (size_t)d * H))[lane] = r;
}

__global__ void agg_kernel() {
    int gw = (blockIdx.x * blockDim.x + threadIdx.x) >> 5;
    int lane = threadIdx.x & 31;
    if (gw >= 2 * ND) return;
    if (gw < ND) agg_body(gw,      g_cnt_b, g_bucket_b, g_Rb, g_B, lane);
    else         agg_body(gw - ND, g_cnt_t, g_bucket_t, g_Rt, g_T, lane);
}

// ================= K3: warp-per-row head =======================================
// D = relu(B@Wbu + T@Wtu + degb*vbb + degt*vbt + bu)
// h = relu(D@oW1 + ob1);  score = sigmoid(h.oW2 + ob2)
__global__ void head_kernel(const float* __restrict__ bu,
                            const float* __restrict__ oW1, const float* __restrict__ ob1,
                            const float* __restrict__ oW2, const float* __restrict__ ob2) {
    __shared__ float sWbu[64 * 64];
    __shared__ float sWtu[64 * 64];
    __shared__ float soW1[64 * 32];
    __shared__ float svbb[64], svbt[64], sbu[64];
    __shared__ float soW2[32], sob1[32];
    __shared__ float sob2;
    __shared__ float sx[8][128];      // per-warp: [0:64)=B row, [64:128)=T row

    int tid = threadIdx.x;
    for (int k = tid; k < 4096; k += 256) { sWbu[k] = g_Wbu[k]; sWtu[k] = g_Wtu[k]; }
    for (int k = tid; k < 2048; k += 256) soW1[k] = __ldg(&oW1[k]);
    if (tid < 64) { svbb[tid] = g_vbb[tid]; svbt[tid] = g_vbt[tid]; sbu[tid] = __ldg(&bu[tid]); }
    if (tid < 32) { soW2[tid] = __ldg(&oW2[tid]); sob1[tid] = __ldg(&ob1[tid]); }
    if (tid == 0) sob2 = __ldg(ob2);
    __syncthreads();

    int w = tid >> 5;
    int lane = tid & 31;

    for (int row = blockIdx.x * 8 + w; row < ND; row += gridDim.x * 8) {
        sx[w][lane]      = g_B[(size_t)row * 64 + lane];
        sx[w][lane + 32] = g_B[(size_t)row * 64 + 32 + lane];
        sx[w][lane + 64] = g_T[(size_t)row * 64 + lane];
        sx[w][lane + 96] = g_T[(size_t)row * 64 + 32 + lane];
        float degb = (float)g_cnt_b[row];
        float degt = (float)g_cnt_t[row];
        __syncwarp();

        int j0 = lane, j1 = lane + 32;
        float acc0 = degb * svbb[j0] + degt * svbt[j0] + sbu[j0];
        float acc1 = degb * svbb[j1] + degt * svbt[j1] + sbu[j1];
        #pragma unroll
        for (int k = 0; k < 64; k++) {
            float xb = sx[w][k];
            float xt = sx[w][64 + k];
            acc0 += xb * sWbu[k * 64 + j0] + xt * sWtu[k * 64 + j0];
            acc1 += xb * sWbu[k * 64 + j1] + xt * sWtu[k * 64 + j1];
        }
        float d0 = fmaxf(acc0, 0.f);   // D[lane]
        float d1 = fmaxf(acc1, 0.f);   // D[lane+32]

        // layer 2: h[lane] (32 outputs), D broadcast via shuffle
        float h = sob1[lane];
        #pragma unroll
        for (int k = 0; k < 32; k++) {
            float dk = __shfl_sync(0xffffffffu, d0, k);
            h += dk * soW1[k * 32 + lane];
        }
        #pragma unroll
        for (int k = 0; k < 32; k++) {
            float dk = __shfl_sync(0xffffffffu, d1, k);
            h += dk * soW1[(k + 32) * 32 + lane];
        }
        h = fmaxf(h, 0.f);

        float p = h * soW2[lane];
        #pragma unroll
        for (int o = 16; o > 0; o >>= 1)
            p += __shfl_down_sync(0xffffffffu, p, o);
        if (lane == 0)
            g_score[row] = 1.f / (1.f + expf(-(p + sob2)));
        __syncwarp();
    }
}

// ================= K4: output gather, float4 writes ============================
__global__ void out_gather_kernel(const int* __restrict__ inst2type,
                                  float* __restrict__ out, int n) {
    int n4 = n >> 2;
    int i = blockIdx.x * blockDim.x + threadIdx.x;
    int stride = gridDim.x * blockDim.x;
    for (int g = i; g < n4; g += stride) {
        int4 t = ((const int4*)inst2type)[g];
        float4 r;
        r.x = g_score[t.x];
        r.y = g_score[t.y];
        r.z = g_score[t.z];
        r.w = g_score[t.w];
        ((float4*)out)[g] = r;
    }
    int rem = n & 3;
    if (i < rem)
        out[n - 1 - i] = g_score[inst2type[n - 1 - i]];
}

// ================= launch ======================================================
extern "C" void kernel_launch(void* const* d_in, const int* in_sizes, int n_in,
                              void* d_out, int out_size) {
    const int*   bene_ids      = (const int*)d_in[0];
    const int*   treatment_ids = (const int*)d_in[2];
    const int*   b2d_src       = (const int*)d_in[3];
    const int*   b2d_dst       = (const int*)d_in[4];
    const int*   t2d_src       = (const int*)d_in[5];
    const int*   t2d_dst       = (const int*)d_in[6];
    const int*   inst2type     = (const int*)d_in[7];
    const float* bene_emb      = (const float*)d_in[8];
    const float* treat_emb     = (const float*)d_in[10];
    const float* Wb1 = (const float*)d_in[17];
    const float* bb1 = (const float*)d_in[18];
    const float* Wt1 = (const float*)d_in[19];
    const float* bt1 = (const float*)d_in[20];
    const float* Wu1 = (const float*)d_in[21];
    const float* bu1 = (const float*)d_in[22];
    const float* oW1 = (const float*)d_in[23];
    const float* ob1 = (const float*)d_in[24];
    const float* oW2 = (const float*)d_in[25];
    const float* ob2 = (const float*)d_in[26];

    int E     = in_sizes[3];
    int NINST = in_sizes[7];

    // K0: weight fold (33 blocks) + zero/convert (160 blocks)
    prep_kernel<<<33 + 160, 256>>>(bene_emb, treat_emb, Wb1, bb1, Wt1, bt1, Wu1);

    {
        int blocks = (2 * (E >> 3) + 255) / 256;
        if (blocks > 2048) blocks = 2048;
        if (blocks < 1) blocks = 1;
        scatter_kernel<<<blocks, 256>>>(b2d_src, b2d_dst, bene_ids,
                                        t2d_src, t2d_dst, treatment_ids, E);
    }
    {
        int blocks = (2 * ND * 32 + 255) / 256;   // one warp per dst segment
        agg_kernel<<<blocks, 256>>>();
    }
    head_kernel<<<313, 256>>>(bu1, oW1, ob1, oW2, ob2);
    {
        int blocks = ((NINST >> 2) + 255) / 256;
        if (blocks < 1) blocks = 1;
        out_gather_kernel<<<blocks, 256>>>(inst2type, (float*)d_out, NINST);
    }
}

// round 9
// speedup vs baseline: 1.6151x; 1.0985x over previous
#include <cuda_runtime.h>
#include <cuda_bf16.h>
#include <math.h>

#define ND 10000
#define NB_EMB 10000
#define NT_EMB 1000
#define H 64
#define CAP 256            // bucket capacity per dst (mean deg 100, max ~143)

// ---------------- device scratch ---------------------------------------------
__device__ int   g_cnt_b[ND];
__device__ int   g_cnt_t[ND];
__device__ int   g_bucket_b[ND * CAP];
__device__ int   g_bucket_t[ND * CAP];
__device__ __nv_bfloat16 g_Rb[NB_EMB * H];
__device__ __nv_bfloat16 g_Rt[NT_EMB * H];
__device__ float g_B[ND * H];
__device__ float g_T[ND * H];
__device__ float2 g_W2[H * H];   // interleaved (0.5*Wb@Wu, 0.5*Wt@Wu)
__device__ float g_vbb[H];       // 0.5 * bb1 @ Wu1
__device__ float g_vbt[H];       // 0.5 * bt1 @ Wu1
__device__ float g_score[ND];

// ================= K0: precompute + zero counters + relu/bf16 convert =========
__global__ void prep_kernel(const float* __restrict__ be,
                            const float* __restrict__ te,
                            const float* __restrict__ Wb, const float* __restrict__ bb,
                            const float* __restrict__ Wt, const float* __restrict__ bt,
                            const float* __restrict__ Wu) {
    if (blockIdx.x < 16) {
        // fold both matrices into interleaved float2
        int t = blockIdx.x * 256 + threadIdx.x;      // 0..4095
        int k = t >> 6;
        int j = t & 63;
        float accb = 0.f, acct = 0.f;
        #pragma unroll 16
        for (int m = 0; m < 64; m++) {
            float u = __ldg(&Wu[m * 64 + j]);
            accb += __ldg(&Wb[k * 64 + m]) * u;
            acct += __ldg(&Wt[k * 64 + m]) * u;
        }
        float2 r; r.x = 0.5f * accb; r.y = 0.5f * acct;
        g_W2[k * 64 + j] = r;
    } else if (blockIdx.x == 16) {
        int t = threadIdx.x;
        if (t < 128) {
            int which = t >> 6;                      // 0: vbb, 1: vbt
            int j = t & 63;
            const float* v = which ? bt : bb;
            float acc = 0.f;
            #pragma unroll 16
            for (int m = 0; m < 64; m++)
                acc += __ldg(&v[m]) * __ldg(&Wu[m * 64 + j]);
            (which ? g_vbt : g_vbb)[j] = 0.5f * acc;
        }
    } else {
        int pb = blockIdx.x - 17;
        int pgrid = gridDim.x - 17;
        int tid = pb * blockDim.x + threadIdx.x;
        int stride = pgrid * blockDim.x;
        for (int i = tid; i < 2 * ND; i += stride) {
            if (i < ND) g_cnt_b[i] = 0;
            else        g_cnt_t[i - ND] = 0;
        }
        for (int i = tid; i < NB_EMB * H; i += stride)
            g_Rb[i] = __float2bfloat16(fmaxf(be[i], 0.f));
        for (int i = tid; i < NT_EMB * H; i += stride)
            g_Rt[i] = __float2bfloat16(fmaxf(te[i], 0.f));
    }
}

// ================= K1: bucket scatter, both edge sets, 8 edges/thread =========
__global__ void scatter_kernel(const int* __restrict__ srcb, const int* __restrict__ dstb,
                               const int* __restrict__ idsb,
                               const int* __restrict__ srct, const int* __restrict__ dstt,
                               const int* __restrict__ idst, int n) {
    int n8 = n >> 3;
    int total = 2 * n8;
    int g = blockIdx.x * blockDim.x + threadIdx.x;
    int stride = gridDim.x * blockDim.x;
    for (int i = g; i < total; i += stride) {
        int which = (i >= n8);
        int gg = which ? i - n8 : i;
        const int4* s4 = (const int4*)(which ? srct : srcb);
        const int4* d4 = (const int4*)(which ? dstt : dstb);
        const int* ids = which ? idst : idsb;
        int* cnt = which ? g_cnt_t : g_cnt_b;
        int* bkt = which ? g_bucket_t : g_bucket_b;
        int4 da = d4[gg * 2], db = d4[gg * 2 + 1];
        int4 sa = s4[gg * 2], sb = s4[gg * 2 + 1];
        int p0 = atomicAdd(&cnt[da.x], 1);
        int p1 = atomicAdd(&cnt[da.y], 1);
        int p2 = atomicAdd(&cnt[da.z], 1);
        int p3 = atomicAdd(&cnt[da.w], 1);
        int p4 = atomicAdd(&cnt[db.x], 1);
        int p5 = atomicAdd(&cnt[db.y], 1);
        int p6 = atomicAdd(&cnt[db.z], 1);
        int p7 = atomicAdd(&cnt[db.w], 1);
        int v0 = __ldg(&ids[sa.x]);
        int v1 = __ldg(&ids[sa.y]);
        int v2 = __ldg(&ids[sa.z]);
        int v3 = __ldg(&ids[sa.w]);
        int v4 = __ldg(&ids[sb.x]);
        int v5 = __ldg(&ids[sb.y]);
        int v6 = __ldg(&ids[sb.z]);
        int v7 = __ldg(&ids[sb.w]);
        bkt[da.x * CAP + p0] = v0;
        bkt[da.y * CAP + p1] = v1;
        bkt[da.z * CAP + p2] = v2;
        bkt[da.w * CAP + p3] = v3;
        bkt[db.x * CAP + p4] = v4;
        bkt[db.y * CAP + p5] = v5;
        bkt[db.z * CAP + p6] = v6;
        bkt[db.w * CAP + p7] = v7;
    }
    int rem = n & 7;
    if (g < rem) {
        int i = n - 1 - g;
        int pb = atomicAdd(&g_cnt_b[dstb[i]], 1);
        g_bucket_b[dstb[i] * CAP + pb] = idsb[srcb[i]];
        int pt = atomicAdd(&g_cnt_t[dstt[i]], 1);
        g_bucket_t[dstt[i] * CAP + pt] = idst[srct[i]];
    }
}

// ================= K2: segment aggregation, one warp per dst ===================
__device__ __forceinline__ void agg_body(
    int d, const int* __restrict__ cnt, const int* __restrict__ bkt,
    const __nv_bfloat16* __restrict__ emb, float* out, int lane)
{
    int s = d * CAP;
    int n = cnt[d];
    float ax = 0.f, ay = 0.f;
    int i = 0;
    for (; i + 8 <= n; i += 8) {
        int id[8];
        #pragma unroll
        for (int k = 0; k < 8; k++) id[k] = __ldg(&bkt[s + i + k]);
        __nv_bfloat162 v[8];
        #pragma unroll
        for (int k = 0; k < 8; k++)
            v[k] = __ldg((const __nv_bfloat162*)(emb + (size_t)id[k] * H) + lane);
        #pragma unroll
        for (int k = 0; k < 8; k++) {
            float2 f = __bfloat1622float2(v[k]);
            ax += f.x; ay += f.y;
        }
    }
    for (; i < n; i++) {
        int id = __ldg(&bkt[s + i]);
        float2 f = __bfloat1622float2(
            __ldg((const __nv_bfloat162*)(emb + (size_t)id * H) + lane));
        ax += f.x; ay += f.y;
    }
    float2 r; r.x = ax; r.y = ay;
    ((float2*)(out + (size_t)d * H))[lane] = r;
}

__global__ void agg_kernel() {
    int gw = (blockIdx.x * blockDim.x + threadIdx.x) >> 5;
    int lane = threadIdx.x & 31;
    if (gw >= 2 * ND) return;
    if (gw < ND) agg_body(gw,      g_cnt_b, g_bucket_b, g_Rb, g_B, lane);
    else         agg_body(gw - ND, g_cnt_t, g_bucket_t, g_Rt, g_T, lane);
}

// ================= K3: head — 4 rows per warp, x in regs, weights float2 ======
__global__ void head_kernel(const float* __restrict__ bu,
                            const float* __restrict__ oW1, const float* __restrict__ ob1,
                            const float* __restrict__ oW2, const float* __restrict__ ob2) {
    __shared__ float2 sW[64 * 64];    // 32 KB, (Wbu, Wtu) interleaved
    __shared__ float soW1[64 * 32];   // 8 KB
    __shared__ float svbb[64], svbt[64], sbu[64];
    __shared__ float soW2[32], sob1[32];
    __shared__ float sob2;

    int tid = threadIdx.x;
    for (int k = tid; k < 4096; k += 256) sW[k] = g_W2[k];
    for (int k = tid; k < 2048; k += 256) soW1[k] = __ldg(&oW1[k]);
    if (tid < 64) { svbb[tid] = g_vbb[tid]; svbt[tid] = g_vbt[tid]; sbu[tid] = __ldg(&bu[tid]); }
    if (tid < 32) { soW2[tid] = __ldg(&oW2[tid]); sob1[tid] = __ldg(&ob1[tid]); }
    if (tid == 0) sob2 = __ldg(ob2);
    __syncthreads();

    int w = tid >> 5;
    int lane = tid & 31;
    int j0 = lane, j1 = lane + 32;

    for (int base = (blockIdx.x * 8 + w) * 4; base < ND; base += gridDim.x * 32) {
        // load 4 rows of B||T into registers (lane-distributed)
        float xb0[4], xb1[4], xt0[4], xt1[4];
        float acc0[4], acc1[4];
        #pragma unroll
        for (int r = 0; r < 4; r++) {
            int row = base + r;
            int rv = (row < ND) ? row : base;   // clamp: duplicate work, guarded write
            xb0[r] = g_B[(size_t)rv * 64 + lane];
            xb1[r] = g_B[(size_t)rv * 64 + 32 + lane];
            xt0[r] = g_T[(size_t)rv * 64 + lane];
            xt1[r] = g_T[(size_t)rv * 64 + 32 + lane];
            float degb = (float)g_cnt_b[rv];
            float degt = (float)g_cnt_t[rv];
            acc0[r] = degb * svbb[j0] + degt * svbt[j0] + sbu[j0];
            acc1[r] = degb * svbb[j1] + degt * svbt[j1] + sbu[j1];
        }

        // layer 1: k = 0..31 from (xb0, xt0)
        #pragma unroll
        for (int k = 0; k < 32; k++) {
            float2 w0 = sW[k * 64 + j0];
            float2 w1 = sW[k * 64 + j1];
            #pragma unroll
            for (int r = 0; r < 4; r++) {
                float xb = __shfl_sync(0xffffffffu, xb0[r], k);
                float xt = __shfl_sync(0xffffffffu, xt0[r], k);
                acc0[r] += xb * w0.x + xt * w0.y;
                acc1[r] += xb * w1.x + xt * w1.y;
            }
        }
        // layer 1: k = 32..63 from (xb1, xt1)
        #pragma unroll
        for (int k = 0; k < 32; k++) {
            float2 w0 = sW[(k + 32) * 64 + j0];
            float2 w1 = sW[(k + 32) * 64 + j1];
            #pragma unroll
            for (int r = 0; r < 4; r++) {
                float xb = __shfl_sync(0xffffffffu, xb1[r], k);
                float xt = __shfl_sync(0xffffffffu, xt1[r], k);
                acc0[r] += xb * w0.x + xt * w0.y;
                acc1[r] += xb * w1.x + xt * w1.y;
            }
        }

        // layer 2 + output, per row
        #pragma unroll
        for (int r = 0; r < 4; r++) {
            float d0 = fmaxf(acc0[r], 0.f);
            float d1 = fmaxf(acc1[r], 0.f);
            float h = sob1[lane];
            #pragma unroll
            for (int k = 0; k < 32; k++) {
                float dk = __shfl_sync(0xffffffffu, d0, k);
                h += dk * soW1[k * 32 + lane];
            }
            #pragma unroll
            for (int k = 0; k < 32; k++) {
                float dk = __shfl_sync(0xffffffffu, d1, k);
                h += dk * soW1[(k + 32) * 32 + lane];
            }
            h = fmaxf(h, 0.f);
            float p = h * soW2[lane];
            #pragma unroll
            for (int o = 16; o > 0; o >>= 1)
                p += __shfl_down_sync(0xffffffffu, p, o);
            if (lane == 0 && base + r < ND)
                g_score[base + r] = 1.f / (1.f + expf(-(p + sob2)));
        }
    }
}

// ================= K4: output gather, float4 writes ============================
__global__ void out_gather_kernel(const int* __restrict__ inst2type,
                                  float* __restrict__ out, int n) {
    int n4 = n >> 2;
    int i = blockIdx.x * blockDim.x + threadIdx.x;
    int stride = gridDim.x * blockDim.x;
    for (int g = i; g < n4; g += stride) {
        int4 t = ((const int4*)inst2type)[g];
        float4 r;
        r.x = g_score[t.x];
        r.y = g_score[t.y];
        r.z = g_score[t.z];
        r.w = g_score[t.w];
        ((float4*)out)[g] = r;
    }
    int rem = n & 3;
    if (i < rem)
        out[n - 1 - i] = g_score[inst2type[n - 1 - i]];
}

// ================= launch ======================================================
extern "C" void kernel_launch(void* const* d_in, const int* in_sizes, int n_in,
                              void* d_out, int out_size) {
    const int*   bene_ids      = (const int*)d_in[0];
    const int*   treatment_ids = (const int*)d_in[2];
    const int*   b2d_src       = (const int*)d_in[3];
    const int*   b2d_dst       = (const int*)d_in[4];
    const int*   t2d_src       = (const int*)d_in[5];
    const int*   t2d_dst       = (const int*)d_in[6];
    const int*   inst2type     = (const int*)d_in[7];
    const float* bene_emb      = (const float*)d_in[8];
    const float* treat_emb     = (const float*)d_in[10];
    const float* Wb1 = (const float*)d_in[17];
    const float* bb1 = (const float*)d_in[18];
    const float* Wt1 = (const float*)d_in[19];
    const float* bt1 = (const float*)d_in[20];
    const float* Wu1 = (const float*)d_in[21];
    const float* bu1 = (const float*)d_in[22];
    const float* oW1 = (const float*)d_in[23];
    const float* ob1 = (const float*)d_in[24];
    const float* oW2 = (const float*)d_in[25];
    const float* ob2 = (const float*)d_in[26];

    int E     = in_sizes[3];
    int NINST = in_sizes[7];

    // K0: weight fold (17 blocks) + zero/convert (160 blocks)
    prep_kernel<<<17 + 160, 256>>>(bene_emb, treat_emb, Wb1, bb1, Wt1, bt1, Wu1);

    {
        int blocks = (2 * (E >> 3) + 255) / 256;
        if (blocks > 2048) blocks = 2048;
        if (blocks < 1) blocks = 1;
        scatter_kernel<<<blocks, 256>>>(b2d_src, b2d_dst, bene_ids,
                                        t2d_src, t2d_dst, treatment_ids, E);
    }
    {
        int blocks = (2 * ND * 32 + 255) / 256;   // one warp per dst segment
        agg_kernel<<<blocks, 256>>>();
    }
    head_kernel<<<313, 256>>>(bu1, oW1, ob1, oW2, ob2);
    {
        int blocks = ((NINST >> 2) + 255) / 256;
        if (blocks < 1) blocks = 1;
        out_gather_kernel<<<blocks, 256>>>(inst2type, (float*)d_out, NINST);
    }
}